// round 14
// baseline (speedup 1.0000x reference)
#include <cuda_runtime.h>
#include <cuda_bf16.h>
#include <cuda_fp16.h>
#include <mma.h>
#include <cstdint>

using namespace nvcuda;

static constexpr int BATCH = 4;
static constexpr int NTOK  = 4096;   // H*W
static constexpr int CH    = 512;
static constexpr int FGD   = 64;

static constexpr long long O_ELEMS = (long long)BATCH * NTOK * CH;    // 8388608
static constexpr long long B_ELEMS = (long long)BATCH * NTOK * NTOK;  // 67108864
static constexpr long long B_PER_BATCH = (long long)NTOK * NTOK;      // 16777216

// ---------------- scratch (static __device__ -- no allocations allowed) ----------
__device__ float  d_f[(size_t)BATCH * NTOK * FGD];
__device__ float  d_g[(size_t)BATCH * NTOK * FGD];
__device__ __half d_h16[(size_t)BATCH * NTOK * CH];          // h in fp16 (h >= 0)
__device__ __half d_betah[(size_t)BATCH * NTOK * NTOK];      // beta in fp16
__device__ float  d_oatt[(size_t)BATCH * NTOK * CH];
__device__ float  d_rowm[BATCH * NTOK];
__device__ float  d_rowl[BATCH * NTOK];
__device__ float  d_beta_scratch[(size_t)BATCH * NTOK * NTOK]; // only if harness wants o-only

// ---------------- bf16 split helper (x = hi + lo, ~17-bit effective mantissa) ----
__device__ __forceinline__ void split4(const float4 v, __nv_bfloat16* hi, __nv_bfloat16* lo) {
    hi[0] = __float2bfloat16(v.x); lo[0] = __float2bfloat16(v.x - __bfloat162float(hi[0]));
    hi[1] = __float2bfloat16(v.y); lo[1] = __float2bfloat16(v.y - __bfloat162float(hi[1]));
    hi[2] = __float2bfloat16(v.z); lo[2] = __float2bfloat16(v.z - __bfloat162float(hi[2]));
    hi[3] = __float2bfloat16(v.w); lo[3] = __float2bfloat16(v.w - __bfloat162float(hi[3]));
}

// ---------------- cp.async helpers (Ampere path, valid on sm_103) ----------------
__device__ __forceinline__ uint32_t smem_u32(const void* p) {
    uint32_t a;
    asm("{ .reg .u64 t; cvta.to.shared.u64 t, %1; cvt.u32.u64 %0, t; }" : "=r"(a) : "l"(p));
    return a;
}
__device__ __forceinline__ void cp_async16(uint32_t dst, const void* src) {
    asm volatile("cp.async.cg.shared.global [%0], [%1], 16;" :: "r"(dst), "l"(src));
}
__device__ __forceinline__ void cp_commit() {
    asm volatile("cp.async.commit_group;");
}
template <int N>
__device__ __forceinline__ void cp_wait() {
    asm volatile("cp.async.wait_group %0;" :: "n"(N));
}

// ================== generic GEMM v2: C = act(A[M,K] @ B[K,N] + bias) ==============
static constexpr int GBM = 128, GBN = 64, GBK = 32;
static constexpr int ALD = GBK + 8;   // 40
static constexpr int BLD = GBN + 8;   // 72
static constexpr int CLD = GBN + 4;   // 68
static constexpr int G_AHALF = GBM * ALD;              // 5120
static constexpr int G_BHALF = GBK * BLD;              // 2304
static constexpr int G_STAGE = 2 * G_AHALF + 2 * G_BHALF;   // 14848 bf16
static constexpr int GEMM_SMEM = 2 * G_STAGE * 2;      // 59392 B

__global__ void __launch_bounds__(256)
gemm_split_kernel(const float* __restrict__ A, const float* __restrict__ B,
                  const float* __restrict__ bias, float* __restrict__ C,
                  __half* __restrict__ C16,
                  int K, int N, int relu)
{
    extern __shared__ __align__(16) unsigned char gsm[];
    float* Csm = reinterpret_cast<float*>(gsm);

    const int m0  = blockIdx.y * GBM;
    const int n0  = blockIdx.x * GBN;
    const int tid = threadIdx.x;
    const int wid = tid >> 5;
    const int wm  = wid >> 1;
    const int wn  = wid & 1;

    wmma::fragment<wmma::accumulator, 16, 16, 16, float> acc[2][2];
    #pragma unroll
    for (int i = 0; i < 2; i++)
        #pragma unroll
        for (int j = 0; j < 2; j++)
            wmma::fill_fragment(acc[i][j], 0.0f);

    const int NCHUNK = K >> 5;
    float4 ra[4], rb[2];

    #pragma unroll
    for (int i = 0; i < 4; i++) {
        int idx = tid + i * 256;
        int row = idx >> 3;
        int c4  = (idx & 7) << 2;
        ra[i] = *reinterpret_cast<const float4*>(A + (long long)(m0 + row) * K + c4);
    }
    #pragma unroll
    for (int i = 0; i < 2; i++) {
        int idx = tid + i * 256;
        int row = idx >> 4;
        int c4  = (idx & 15) << 2;
        rb[i] = *reinterpret_cast<const float4*>(B + (long long)row * N + n0 + c4);
    }

    #pragma unroll 1
    for (int c = 0; c < NCHUNK; c++) {
        __nv_bfloat16* stage = reinterpret_cast<__nv_bfloat16*>(gsm) + (c & 1) * G_STAGE;
        __nv_bfloat16* Ahi = stage;
        __nv_bfloat16* Alo = Ahi + G_AHALF;
        __nv_bfloat16* Bhi = Alo + G_AHALF;
        __nv_bfloat16* Blo = Bhi + G_BHALF;

        #pragma unroll
        for (int i = 0; i < 4; i++) {
            int idx = tid + i * 256;
            int row = idx >> 3;
            int c4  = (idx & 7) << 2;
            split4(ra[i], &Ahi[row * ALD + c4], &Alo[row * ALD + c4]);
        }
        #pragma unroll
        for (int i = 0; i < 2; i++) {
            int idx = tid + i * 256;
            int row = idx >> 4;
            int c4  = (idx & 15) << 2;
            split4(rb[i], &Bhi[row * BLD + c4], &Blo[row * BLD + c4]);
        }
        __syncthreads();

        if (c + 1 < NCHUNK) {
            const long long k0 = (long long)(c + 1) << 5;
            #pragma unroll
            for (int i = 0; i < 4; i++) {
                int idx = tid + i * 256;
                int row = idx >> 3;
                int c4  = (idx & 7) << 2;
                ra[i] = *reinterpret_cast<const float4*>(A + (long long)(m0 + row) * K + k0 + c4);
            }
            #pragma unroll
            for (int i = 0; i < 2; i++) {
                int idx = tid + i * 256;
                int row = idx >> 4;
                int c4  = (idx & 15) << 2;
                rb[i] = *reinterpret_cast<const float4*>(B + (k0 + row) * N + n0 + c4);
            }
        }

        #pragma unroll
        for (int ks = 0; ks < 2; ks++) {
            wmma::fragment<wmma::matrix_a, 16, 16, 16, __nv_bfloat16, wmma::row_major> ah[2], al[2];
            wmma::fragment<wmma::matrix_b, 16, 16, 16, __nv_bfloat16, wmma::row_major> bh[2], bl[2];
            #pragma unroll
            for (int r2 = 0; r2 < 2; r2++) {
                wmma::load_matrix_sync(ah[r2], &Ahi[(wm * 32 + r2 * 16) * ALD + ks * 16], ALD);
                wmma::load_matrix_sync(al[r2], &Alo[(wm * 32 + r2 * 16) * ALD + ks * 16], ALD);
            }
            #pragma unroll
            for (int cn = 0; cn < 2; cn++) {
                wmma::load_matrix_sync(bh[cn], &Bhi[(ks * 16) * BLD + wn * 32 + cn * 16], BLD);
                wmma::load_matrix_sync(bl[cn], &Blo[(ks * 16) * BLD + wn * 32 + cn * 16], BLD);
            }
            #pragma unroll
            for (int r2 = 0; r2 < 2; r2++)
                #pragma unroll
                for (int cn = 0; cn < 2; cn++) {
                    wmma::mma_sync(acc[r2][cn], ah[r2], bh[cn], acc[r2][cn]);
                    wmma::mma_sync(acc[r2][cn], ah[r2], bl[cn], acc[r2][cn]);
                    wmma::mma_sync(acc[r2][cn], al[r2], bh[cn], acc[r2][cn]);
                }
        }
    }

    __syncthreads();
    #pragma unroll
    for (int r2 = 0; r2 < 2; r2++)
        #pragma unroll
        for (int cn = 0; cn < 2; cn++)
            wmma::store_matrix_sync(&Csm[(wm * 32 + r2 * 16) * CLD + wn * 32 + cn * 16],
                                    acc[r2][cn], CLD, wmma::mem_row_major);
    __syncthreads();

    #pragma unroll
    for (int i = 0; i < 8; i++) {
        int idx = tid + i * 256;
        int row = idx >> 4;
        int c4  = (idx & 15) << 2;
        float4 v = *reinterpret_cast<const float4*>(&Csm[row * CLD + c4]);
        if (bias != nullptr) {
            float4 bv = *reinterpret_cast<const float4*>(bias + n0 + c4);
            v.x += bv.x; v.y += bv.y; v.z += bv.z; v.w += bv.w;
        }
        if (relu) {
            v.x = fmaxf(v.x, 0.f); v.y = fmaxf(v.y, 0.f);
            v.z = fmaxf(v.z, 0.f); v.w = fmaxf(v.w, 0.f);
        }
        if (C16 != nullptr) {
            __half2 h01 = __floats2half2_rn(v.x, v.y);
            __half2 h23 = __floats2half2_rn(v.z, v.w);
            uint2 p;
            p.x = *reinterpret_cast<uint32_t*>(&h01);
            p.y = *reinterpret_cast<uint32_t*>(&h23);
            *reinterpret_cast<uint2*>(C16 + (long long)(m0 + row) * N + n0 + c4) = p;
        } else {
            *reinterpret_cast<float4*>(C + (long long)(m0 + row) * N + n0 + c4) = v;
        }
    }
}

// ================== PV GEMM v4 (proven best): 128x64, KC=64, cp.async ============
// Pointers pre-offset per batch; grid (8, 32, 1).
static constexpr int PALD = 72;
static constexpr int PBLD = 72;
static constexpr int PV_ABUF = 128 * PALD;
static constexpr int PV_BBUF = 64 * PBLD;
static constexpr int PV_STAGE = PV_ABUF + PV_BBUF;  // 13824 halves
static constexpr int PV_SMEM = 2 * PV_STAGE * 2;    // 55296 B
static constexpr int PV_NCHUNK = NTOK / 64;         // 64

__global__ void __launch_bounds__(256)
pv_f16s_kernel(const __half* __restrict__ A, const __half* __restrict__ B,
               float* __restrict__ C)
{
    extern __shared__ __align__(16) __half pvsm[];

    const int m0  = blockIdx.y * 128;
    const int n0  = blockIdx.x * 64;
    const int tid = threadIdx.x;
    const int wid = tid >> 5;
    const int wm  = wid >> 1;
    const int wn  = wid & 1;

    const uint32_t smbase = smem_u32(pvsm);

    auto issue_chunk = [&](int c) {
        const int buf = c & 1;
        uint32_t sa = smbase + (uint32_t)(buf * PV_STAGE) * 2;
        uint32_t sb = sa + (uint32_t)PV_ABUF * 2;
        const long long k0 = (long long)c * 64;
        #pragma unroll
        for (int i = 0; i < 4; i++) {
            int idx = tid + i * 256;
            int row = idx >> 3;
            int c8  = (idx & 7) << 3;
            cp_async16(sa + (uint32_t)(row * PALD + c8) * 2,
                       A + (long long)(m0 + row) * NTOK + k0 + c8);
        }
        #pragma unroll
        for (int i = 0; i < 2; i++) {
            int idx = tid + i * 256;
            int row = idx >> 3;
            int c8  = (idx & 7) << 3;
            cp_async16(sb + (uint32_t)(row * PBLD + c8) * 2,
                       B + (long long)(k0 + row) * CH + n0 + c8);
        }
        cp_commit();
    };

    wmma::fragment<wmma::accumulator, 16, 16, 16, float> acc[2][2];
    #pragma unroll
    for (int i = 0; i < 2; i++)
        #pragma unroll
        for (int j = 0; j < 2; j++)
            wmma::fill_fragment(acc[i][j], 0.0f);

    issue_chunk(0);

    #pragma unroll 1
    for (int c = 0; c < PV_NCHUNK; c++) {
        if (c + 1 < PV_NCHUNK) {
            issue_chunk(c + 1);
            cp_wait<1>();
        } else {
            cp_wait<0>();
        }
        __syncthreads();

        const __half* Af = pvsm + (c & 1) * PV_STAGE;
        const __half* Bf = Af + PV_ABUF;
        #pragma unroll
        for (int ks = 0; ks < 4; ks++) {
            wmma::fragment<wmma::matrix_a, 16, 16, 16, __half, wmma::row_major> af[2];
            wmma::fragment<wmma::matrix_b, 16, 16, 16, __half, wmma::row_major> bf[2];
            #pragma unroll
            for (int r2 = 0; r2 < 2; r2++)
                wmma::load_matrix_sync(af[r2], &Af[(wm * 32 + r2 * 16) * PALD + ks * 16], PALD);
            #pragma unroll
            for (int cn = 0; cn < 2; cn++)
                wmma::load_matrix_sync(bf[cn], &Bf[(ks * 16) * PBLD + wn * 32 + cn * 16], PBLD);
            #pragma unroll
            for (int r2 = 0; r2 < 2; r2++)
                #pragma unroll
                for (int cn = 0; cn < 2; cn++)
                    wmma::mma_sync(acc[r2][cn], af[r2], bf[cn], acc[r2][cn]);
        }
        __syncthreads();
    }

    #pragma unroll
    for (int r2 = 0; r2 < 2; r2++)
        #pragma unroll
        for (int cn = 0; cn < 2; cn++)
            wmma::store_matrix_sync(C + (long long)(m0 + wm * 32 + r2 * 16) * CH + n0 + wn * 32 + cn * 16,
                                    acc[r2][cn], CH, wmma::mem_row_major);
}

// ======== scores v2: 64-row query tiles, 256 threads; pointers pre-offset ========
static constexpr int SLD = 132;
static constexpr int GLD = 72;
static constexpr int SCORES_SMEM = (2 * 64 * GLD + 2 * 128 * GLD) * 2 + 64 * SLD * 4; // 89088 B

__global__ void __launch_bounds__(256, 2)
scores_kernel(const float* __restrict__ g, const float* __restrict__ f,
              float* __restrict__ sraw, float* __restrict__ rowm, float* __restrict__ rowl)
{
    extern __shared__ unsigned char smraw[];
    __nv_bfloat16* Ghi = reinterpret_cast<__nv_bfloat16*>(smraw);
    __nv_bfloat16* Glo = Ghi + 64 * GLD;
    __nv_bfloat16* Fhi = Glo + 64 * GLD;
    __nv_bfloat16* Flo = Fhi + 128 * GLD;
    float*         S   = reinterpret_cast<float*>(Flo + 128 * GLD);

    const int r0  = blockIdx.x * 64;
    const int tid = threadIdx.x;
    const int wid = tid >> 5;
    const int wm  = wid >> 2;
    const int wn  = wid & 3;

    const float* gbase = g + (long long)r0 * FGD;
    const float* fbase = f;

    #pragma unroll
    for (int i = 0; i < 4; i++) {
        int idx = tid + i * 256;
        int row = idx >> 4;
        int c4  = (idx & 15) << 2;
        float4 v = *reinterpret_cast<const float4*>(gbase + row * FGD + c4);
        split4(v, &Ghi[row * GLD + c4], &Glo[row * GLD + c4]);
    }

    float m_run = -1e30f, l_run = 0.0f;
    const int srow = tid >> 2;
    const int q    = tid & 3;
    const float4* Sscan4 = reinterpret_cast<const float4*>(&S[srow * SLD + q * 32]);

    for (int ci = 0; ci < 32; ci++) {
        __syncthreads();
        #pragma unroll
        for (int i = 0; i < 8; i++) {
            int idx = tid + i * 256;
            int row = idx >> 4;
            int c4  = (idx & 15) << 2;
            float4 v = *reinterpret_cast<const float4*>(fbase + (long long)(ci * 128 + row) * FGD + c4);
            split4(v, &Fhi[row * GLD + c4], &Flo[row * GLD + c4]);
        }
        __syncthreads();

        wmma::fragment<wmma::accumulator, 16, 16, 16, float> acc[2][2];
        #pragma unroll
        for (int i = 0; i < 2; i++)
            #pragma unroll
            for (int j = 0; j < 2; j++)
                wmma::fill_fragment(acc[i][j], 0.0f);

        #pragma unroll
        for (int ks = 0; ks < 4; ks++) {
            wmma::fragment<wmma::matrix_a, 16, 16, 16, __nv_bfloat16, wmma::row_major> ah[2], al[2];
            wmma::fragment<wmma::matrix_b, 16, 16, 16, __nv_bfloat16, wmma::col_major> bh[2], bl[2];
            #pragma unroll
            for (int r2 = 0; r2 < 2; r2++) {
                wmma::load_matrix_sync(ah[r2], &Ghi[(wm * 32 + r2 * 16) * GLD + ks * 16], GLD);
                wmma::load_matrix_sync(al[r2], &Glo[(wm * 32 + r2 * 16) * GLD + ks * 16], GLD);
            }
            #pragma unroll
            for (int cn = 0; cn < 2; cn++) {
                wmma::load_matrix_sync(bh[cn], &Fhi[(wn * 32 + cn * 16) * GLD + ks * 16], GLD);
                wmma::load_matrix_sync(bl[cn], &Flo[(wn * 32 + cn * 16) * GLD + ks * 16], GLD);
            }
            #pragma unroll
            for (int r2 = 0; r2 < 2; r2++)
                #pragma unroll
                for (int cn = 0; cn < 2; cn++) {
                    wmma::mma_sync(acc[r2][cn], ah[r2], bh[cn], acc[r2][cn]);
                    wmma::mma_sync(acc[r2][cn], ah[r2], bl[cn], acc[r2][cn]);
                    wmma::mma_sync(acc[r2][cn], al[r2], bh[cn], acc[r2][cn]);
                }
        }
        #pragma unroll
        for (int r2 = 0; r2 < 2; r2++)
            #pragma unroll
            for (int cn = 0; cn < 2; cn++)
                wmma::store_matrix_sync(&S[(wm * 32 + r2 * 16) * SLD + wn * 32 + cn * 16],
                                        acc[r2][cn], SLD, wmma::mem_row_major);
        __syncthreads();

        size_t gout = (size_t)r0 * NTOK + (size_t)ci * 128;
        #pragma unroll
        for (int i = 0; i < 8; i++) {
            int idx = tid + i * 256;
            int row = idx >> 5;
            int c4  = (idx & 31) << 2;
            float4 v = *reinterpret_cast<const float4*>(&S[row * SLD + c4]);
            *reinterpret_cast<float4*>(sraw + gout + (size_t)row * NTOK + c4) = v;
        }
        float vmax = -1e30f;
        #pragma unroll
        for (int j = 0; j < 8; j++) {
            float4 a = Sscan4[j];
            vmax = fmaxf(vmax, fmaxf(fmaxf(a.x, a.y), fmaxf(a.z, a.w)));
        }
        float mn = fmaxf(m_run, vmax);
        float add = 0.0f;
        #pragma unroll
        for (int j = 0; j < 8; j++) {
            float4 a = Sscan4[j];
            add += __expf(a.x - mn) + __expf(a.y - mn) + __expf(a.z - mn) + __expf(a.w - mn);
        }
        l_run = l_run * __expf(m_run - mn) + add;
        m_run = mn;
    }

    #pragma unroll
    for (int off = 1; off < 4; off <<= 1) {
        float mo  = __shfl_xor_sync(0xffffffffu, m_run, off);
        float lo2 = __shfl_xor_sync(0xffffffffu, l_run, off);
        float mn  = fmaxf(m_run, mo);
        l_run = l_run * __expf(m_run - mn) + lo2 * __expf(mo - mn);
        m_run = mn;
    }
    if (q == 0) {
        rowm[r0 + srow] = m_run;
        rowl[r0 + srow] = l_run;
    }
}

// ============ normalize (per batch): beta = exp(s - m)/l, fp32 + fp16 ===========
__global__ void __launch_bounds__(256)
normalize_kernel(float* __restrict__ beta, __half* __restrict__ betah,
                 const float* __restrict__ rowm, const float* __restrict__ rowl)
{
    long long idx = (long long)blockIdx.x * 256 + threadIdx.x;   // float4 index in batch
    if (idx >= (B_PER_BATCH >> 2)) return;
    int rowg = (int)(idx >> 10);                                 // row within batch
    float m   = __ldg(rowm + rowg);
    float inv = 1.0f / __ldg(rowl + rowg);
    float4 v = *reinterpret_cast<float4*>(beta + idx * 4);
    v.x = __expf(v.x - m) * inv;
    v.y = __expf(v.y - m) * inv;
    v.z = __expf(v.z - m) * inv;
    v.w = __expf(v.w - m) * inv;
    *reinterpret_cast<float4*>(beta + idx * 4) = v;
    __half2 h01 = __floats2half2_rn(v.x, v.y);
    __half2 h23 = __floats2half2_rn(v.z, v.w);
    uint2 p;
    p.x = *reinterpret_cast<uint32_t*>(&h01);
    p.y = *reinterpret_cast<uint32_t*>(&h23);
    *reinterpret_cast<uint2*>(betah + idx * 4) = p;
}

// ================== launch ========================================================
extern "C" void kernel_launch(void* const* d_in, const int* in_sizes, int n_in,
                              void* d_out, int out_size)
{
    (void)in_sizes; (void)n_in;
    const float* l  = (const float*)d_in[0];
    const float* r  = (const float*)d_in[1];
    const float* Wf = (const float*)d_in[2];
    const float* Wg = (const float*)d_in[3];
    const float* Wh = (const float*)d_in[4];
    const float* Wo = (const float*)d_in[5];
    const float* bf = (const float*)d_in[6];
    const float* bg = (const float*)d_in[7];
    const float* bh = (const float*)d_in[8];
    const float* bo = (const float*)d_in[9];
    float* out = (float*)d_out;

    float  *p_f, *p_g, *p_oatt, *p_rowm, *p_rowl, *p_bscr;
    __half *p_h16, *p_betah;
    cudaGetSymbolAddress((void**)&p_f,     d_f);
    cudaGetSymbolAddress((void**)&p_g,     d_g);
    cudaGetSymbolAddress((void**)&p_h16,   d_h16);
    cudaGetSymbolAddress((void**)&p_betah, d_betah);
    cudaGetSymbolAddress((void**)&p_oatt,  d_oatt);
    cudaGetSymbolAddress((void**)&p_rowm,  d_rowm);
    cudaGetSymbolAddress((void**)&p_rowl,  d_rowl);
    cudaGetSymbolAddress((void**)&p_bscr,  d_beta_scratch);

    // output layout: reference returns (o, beta) -> o first, then beta
    float* o_out    = nullptr;
    float* beta_out = nullptr;
    long long osz = (long long)out_size;
    if (osz >= O_ELEMS + B_ELEMS) { o_out = out; beta_out = out + O_ELEMS; }
    else if (osz == B_ELEMS)      { beta_out = out; }
    else                          { o_out = out; beta_out = p_bscr; }

    // one-time setup -- EXACTLY 3 streams (proven zero device-mem delta) + 5 events
    static cudaStream_t s0 = nullptr, s1 = nullptr, s_side = nullptr;
    static cudaEvent_t  ev_root = nullptr, ev_side = nullptr, ev_g = nullptr,
                        ev_j0 = nullptr, ev_j1 = nullptr;
    if (s0 == nullptr) {
        cudaStreamCreateWithFlags(&s0,     cudaStreamNonBlocking);
        cudaStreamCreateWithFlags(&s1,     cudaStreamNonBlocking);
        cudaStreamCreateWithFlags(&s_side, cudaStreamNonBlocking);
        cudaEventCreateWithFlags(&ev_root, cudaEventDisableTiming);
        cudaEventCreateWithFlags(&ev_side, cudaEventDisableTiming);
        cudaEventCreateWithFlags(&ev_g,    cudaEventDisableTiming);
        cudaEventCreateWithFlags(&ev_j0,   cudaEventDisableTiming);
        cudaEventCreateWithFlags(&ev_j1,   cudaEventDisableTiming);
        cudaFuncSetAttribute(scores_kernel, cudaFuncAttributeMaxDynamicSharedMemorySize, SCORES_SMEM);
        cudaFuncSetAttribute(pv_f16s_kernel, cudaFuncAttributeMaxDynamicSharedMemorySize, PV_SMEM);
        cudaFuncSetAttribute(gemm_split_kernel, cudaFuncAttributeMaxDynamicSharedMemorySize, GEMM_SMEM);
    }

    // fork from the capture (default) stream
    cudaEventRecord(ev_root, 0);
    cudaStreamWaitEvent(s0,     ev_root, 0);
    cudaStreamWaitEvent(s1,     ev_root, 0);
    cudaStreamWaitEvent(s_side, ev_root, 0);

    // side stream: h = relu(l @ Wh + bh) as fp16 (only needed by PV)
    gemm_split_kernel<<<dim3(8, 128, 1), 256, GEMM_SMEM, s_side>>>(l, Wh, bh, nullptr, p_h16, 512, 512, 1);
    cudaEventRecord(ev_side, s_side);

    // s0 head: f then g (small; serialized to save an event)
    gemm_split_kernel<<<dim3(1, 128, 1), 256, GEMM_SMEM, s0>>>(l, Wf, bf, p_f, nullptr, 512, 64, 1);
    gemm_split_kernel<<<dim3(1, 128, 1), 256, GEMM_SMEM, s0>>>(r, Wg, bg, p_g, nullptr, 512, 64, 1);
    cudaEventRecord(ev_g, s0);
    cudaStreamWaitEvent(s1, ev_g, 0);

    // per-batch pipelined tail across 2 streams: b0,b2 on s0; b1,b3 on s1
    const int nrm_grid = (int)((B_PER_BATCH >> 2) + 255) / 256;  // 16384
    for (int b = 0; b < BATCH; b++) {
        cudaStream_t st = (b & 1) ? s1 : s0;
        const long long boff  = (long long)b * B_PER_BATCH;
        const long long fgoff = (long long)b * NTOK * FGD;
        const long long hoff  = (long long)b * NTOK * CH;

        scores_kernel<<<dim3(64, 1, 1), 256, SCORES_SMEM, st>>>(
            p_g + fgoff, p_f + fgoff, beta_out + boff, p_rowm + b * NTOK, p_rowl + b * NTOK);
        normalize_kernel<<<nrm_grid, 256, 0, st>>>(
            beta_out + boff, p_betah + boff, p_rowm + b * NTOK, p_rowl + b * NTOK);

        if (o_out) {
            cudaStreamWaitEvent(st, ev_side, 0);
            pv_f16s_kernel<<<dim3(8, 32, 1), 256, PV_SMEM, st>>>(
                p_betah + boff, p_h16 + hoff, p_oatt + hoff);
            gemm_split_kernel<<<dim3(8, 32, 1), 256, GEMM_SMEM, st>>>(
                p_oatt + hoff, Wo, bo, o_out + hoff, nullptr, 512, 512, 1);
        }
    }
    cudaEventRecord(ev_j0, s0);
    cudaEventRecord(ev_j1, s1);

    // join back to the capture stream
    cudaStreamWaitEvent(0, ev_j0, 0);
    cudaStreamWaitEvent(0, ev_j1, 0);
}

// round 15
// speedup vs baseline: 1.0096x; 1.0096x over previous
#include <cuda_runtime.h>
#include <cuda_bf16.h>
#include <cuda_fp16.h>
#include <mma.h>
#include <cstdint>

using namespace nvcuda;

static constexpr int BATCH = 4;
static constexpr int NTOK  = 4096;   // H*W
static constexpr int CH    = 512;
static constexpr int FGD   = 64;

static constexpr long long O_ELEMS = (long long)BATCH * NTOK * CH;    // 8388608
static constexpr long long B_ELEMS = (long long)BATCH * NTOK * NTOK;  // 67108864

// ---------------- scratch (static __device__ -- no allocations allowed) ----------
__device__ float  d_f[(size_t)BATCH * NTOK * FGD];
__device__ float  d_g[(size_t)BATCH * NTOK * FGD];
__device__ __half d_h16[(size_t)BATCH * NTOK * CH];          // h in fp16 (h >= 0)
__device__ __half d_betah[(size_t)BATCH * NTOK * NTOK];      // beta in fp16
__device__ float  d_oatt[(size_t)BATCH * NTOK * CH];
__device__ float  d_beta_scratch[(size_t)BATCH * NTOK * NTOK]; // only if harness wants o-only

// ---------------- bf16 split helper (x = hi + lo, ~17-bit effective mantissa) ----
__device__ __forceinline__ void split4(const float4 v, __nv_bfloat16* hi, __nv_bfloat16* lo) {
    hi[0] = __float2bfloat16(v.x); lo[0] = __float2bfloat16(v.x - __bfloat162float(hi[0]));
    hi[1] = __float2bfloat16(v.y); lo[1] = __float2bfloat16(v.y - __bfloat162float(hi[1]));
    hi[2] = __float2bfloat16(v.z); lo[2] = __float2bfloat16(v.z - __bfloat162float(hi[2]));
    hi[3] = __float2bfloat16(v.w); lo[3] = __float2bfloat16(v.w - __bfloat162float(hi[3]));
}

// ---------------- cp.async helpers (Ampere path, valid on sm_103) ----------------
__device__ __forceinline__ uint32_t smem_u32(const void* p) {
    uint32_t a;
    asm("{ .reg .u64 t; cvta.to.shared.u64 t, %1; cvt.u32.u64 %0, t; }" : "=r"(a) : "l"(p));
    return a;
}
__device__ __forceinline__ void cp_async16(uint32_t dst, const void* src) {
    asm volatile("cp.async.cg.shared.global [%0], [%1], 16;" :: "r"(dst), "l"(src));
}
__device__ __forceinline__ void cp_commit() {
    asm volatile("cp.async.commit_group;");
}
template <int N>
__device__ __forceinline__ void cp_wait() {
    asm volatile("cp.async.wait_group %0;" :: "n"(N));
}

// ================== generic GEMM v2: C = act(A[M,K] @ B[K,N] + bias) ==============
static constexpr int GBM = 128, GBN = 64, GBK = 32;
static constexpr int ALD = GBK + 8;   // 40
static constexpr int BLD = GBN + 8;   // 72
static constexpr int CLD = GBN + 4;   // 68
static constexpr int G_AHALF = GBM * ALD;              // 5120
static constexpr int G_BHALF = GBK * BLD;              // 2304
static constexpr int G_STAGE = 2 * G_AHALF + 2 * G_BHALF;   // 14848 bf16
static constexpr int GEMM_SMEM = 2 * G_STAGE * 2;      // 59392 B

__global__ void __launch_bounds__(256)
gemm_split_kernel(const float* __restrict__ A, const float* __restrict__ B,
                  const float* __restrict__ bias, float* __restrict__ C,
                  __half* __restrict__ C16,
                  int K, int N, int relu)
{
    extern __shared__ __align__(16) unsigned char gsm[];
    float* Csm = reinterpret_cast<float*>(gsm);

    const int m0  = blockIdx.y * GBM;
    const int n0  = blockIdx.x * GBN;
    const int tid = threadIdx.x;
    const int wid = tid >> 5;
    const int wm  = wid >> 1;
    const int wn  = wid & 1;

    wmma::fragment<wmma::accumulator, 16, 16, 16, float> acc[2][2];
    #pragma unroll
    for (int i = 0; i < 2; i++)
        #pragma unroll
        for (int j = 0; j < 2; j++)
            wmma::fill_fragment(acc[i][j], 0.0f);

    const int NCHUNK = K >> 5;
    float4 ra[4], rb[2];

    #pragma unroll
    for (int i = 0; i < 4; i++) {
        int idx = tid + i * 256;
        int row = idx >> 3;
        int c4  = (idx & 7) << 2;
        ra[i] = *reinterpret_cast<const float4*>(A + (long long)(m0 + row) * K + c4);
    }
    #pragma unroll
    for (int i = 0; i < 2; i++) {
        int idx = tid + i * 256;
        int row = idx >> 4;
        int c4  = (idx & 15) << 2;
        rb[i] = *reinterpret_cast<const float4*>(B + (long long)row * N + n0 + c4);
    }

    #pragma unroll 1
    for (int c = 0; c < NCHUNK; c++) {
        __nv_bfloat16* stage = reinterpret_cast<__nv_bfloat16*>(gsm) + (c & 1) * G_STAGE;
        __nv_bfloat16* Ahi = stage;
        __nv_bfloat16* Alo = Ahi + G_AHALF;
        __nv_bfloat16* Bhi = Alo + G_AHALF;
        __nv_bfloat16* Blo = Bhi + G_BHALF;

        #pragma unroll
        for (int i = 0; i < 4; i++) {
            int idx = tid + i * 256;
            int row = idx >> 3;
            int c4  = (idx & 7) << 2;
            split4(ra[i], &Ahi[row * ALD + c4], &Alo[row * ALD + c4]);
        }
        #pragma unroll
        for (int i = 0; i < 2; i++) {
            int idx = tid + i * 256;
            int row = idx >> 4;
            int c4  = (idx & 15) << 2;
            split4(rb[i], &Bhi[row * BLD + c4], &Blo[row * BLD + c4]);
        }
        __syncthreads();

        if (c + 1 < NCHUNK) {
            const long long k0 = (long long)(c + 1) << 5;
            #pragma unroll
            for (int i = 0; i < 4; i++) {
                int idx = tid + i * 256;
                int row = idx >> 3;
                int c4  = (idx & 7) << 2;
                ra[i] = *reinterpret_cast<const float4*>(A + (long long)(m0 + row) * K + k0 + c4);
            }
            #pragma unroll
            for (int i = 0; i < 2; i++) {
                int idx = tid + i * 256;
                int row = idx >> 4;
                int c4  = (idx & 15) << 2;
                rb[i] = *reinterpret_cast<const float4*>(B + (k0 + row) * N + n0 + c4);
            }
        }

        #pragma unroll
        for (int ks = 0; ks < 2; ks++) {
            wmma::fragment<wmma::matrix_a, 16, 16, 16, __nv_bfloat16, wmma::row_major> ah[2], al[2];
            wmma::fragment<wmma::matrix_b, 16, 16, 16, __nv_bfloat16, wmma::row_major> bh[2], bl[2];
            #pragma unroll
            for (int r2 = 0; r2 < 2; r2++) {
                wmma::load_matrix_sync(ah[r2], &Ahi[(wm * 32 + r2 * 16) * ALD + ks * 16], ALD);
                wmma::load_matrix_sync(al[r2], &Alo[(wm * 32 + r2 * 16) * ALD + ks * 16], ALD);
            }
            #pragma unroll
            for (int cn = 0; cn < 2; cn++) {
                wmma::load_matrix_sync(bh[cn], &Bhi[(ks * 16) * BLD + wn * 32 + cn * 16], BLD);
                wmma::load_matrix_sync(bl[cn], &Blo[(ks * 16) * BLD + wn * 32 + cn * 16], BLD);
            }
            #pragma unroll
            for (int r2 = 0; r2 < 2; r2++)
                #pragma unroll
                for (int cn = 0; cn < 2; cn++) {
                    wmma::mma_sync(acc[r2][cn], ah[r2], bh[cn], acc[r2][cn]);
                    wmma::mma_sync(acc[r2][cn], ah[r2], bl[cn], acc[r2][cn]);
                    wmma::mma_sync(acc[r2][cn], al[r2], bh[cn], acc[r2][cn]);
                }
        }
    }

    __syncthreads();
    #pragma unroll
    for (int r2 = 0; r2 < 2; r2++)
        #pragma unroll
        for (int cn = 0; cn < 2; cn++)
            wmma::store_matrix_sync(&Csm[(wm * 32 + r2 * 16) * CLD + wn * 32 + cn * 16],
                                    acc[r2][cn], CLD, wmma::mem_row_major);
    __syncthreads();

    #pragma unroll
    for (int i = 0; i < 8; i++) {
        int idx = tid + i * 256;
        int row = idx >> 4;
        int c4  = (idx & 15) << 2;
        float4 v = *reinterpret_cast<const float4*>(&Csm[row * CLD + c4]);
        if (bias != nullptr) {
            float4 bv = *reinterpret_cast<const float4*>(bias + n0 + c4);
            v.x += bv.x; v.y += bv.y; v.z += bv.z; v.w += bv.w;
        }
        if (relu) {
            v.x = fmaxf(v.x, 0.f); v.y = fmaxf(v.y, 0.f);
            v.z = fmaxf(v.z, 0.f); v.w = fmaxf(v.w, 0.f);
        }
        if (C16 != nullptr) {
            __half2 h01 = __floats2half2_rn(v.x, v.y);
            __half2 h23 = __floats2half2_rn(v.z, v.w);
            uint2 p;
            p.x = *reinterpret_cast<uint32_t*>(&h01);
            p.y = *reinterpret_cast<uint32_t*>(&h23);
            *reinterpret_cast<uint2*>(C16 + (long long)(m0 + row) * N + n0 + c4) = p;
        } else {
            *reinterpret_cast<float4*>(C + (long long)(m0 + row) * N + n0 + c4) = v;
        }
    }
}

// ================== PV GEMM v4 (proven best): 128x64, KC=64, cp.async ============
static constexpr int PALD = 72;
static constexpr int PBLD = 72;
static constexpr int PV_ABUF = 128 * PALD;
static constexpr int PV_BBUF = 64 * PBLD;
static constexpr int PV_STAGE = PV_ABUF + PV_BBUF;  // 13824 halves
static constexpr int PV_SMEM = 2 * PV_STAGE * 2;    // 55296 B
static constexpr int PV_NCHUNK = NTOK / 64;         // 64

__global__ void __launch_bounds__(256)
pv_f16s_kernel(const __half* __restrict__ betah, const __half* __restrict__ h16,
               float* __restrict__ oatt)
{
    extern __shared__ __align__(16) __half pvsm[];

    const __half* A = betah + (long long)blockIdx.z * NTOK * NTOK;
    const __half* B = h16   + (long long)blockIdx.z * NTOK * CH;
    float*        C = oatt  + (long long)blockIdx.z * NTOK * CH;
    const int m0  = blockIdx.y * 128;
    const int n0  = blockIdx.x * 64;
    const int tid = threadIdx.x;
    const int wid = tid >> 5;
    const int wm  = wid >> 1;
    const int wn  = wid & 1;

    const uint32_t smbase = smem_u32(pvsm);

    auto issue_chunk = [&](int c) {
        const int buf = c & 1;
        uint32_t sa = smbase + (uint32_t)(buf * PV_STAGE) * 2;
        uint32_t sb = sa + (uint32_t)PV_ABUF * 2;
        const long long k0 = (long long)c * 64;
        #pragma unroll
        for (int i = 0; i < 4; i++) {
            int idx = tid + i * 256;
            int row = idx >> 3;
            int c8  = (idx & 7) << 3;
            cp_async16(sa + (uint32_t)(row * PALD + c8) * 2,
                       A + (long long)(m0 + row) * NTOK + k0 + c8);
        }
        #pragma unroll
        for (int i = 0; i < 2; i++) {
            int idx = tid + i * 256;
            int row = idx >> 3;
            int c8  = (idx & 7) << 3;
            cp_async16(sb + (uint32_t)(row * PBLD + c8) * 2,
                       B + (long long)(k0 + row) * CH + n0 + c8);
        }
        cp_commit();
    };

    wmma::fragment<wmma::accumulator, 16, 16, 16, float> acc[2][2];
    #pragma unroll
    for (int i = 0; i < 2; i++)
        #pragma unroll
        for (int j = 0; j < 2; j++)
            wmma::fill_fragment(acc[i][j], 0.0f);

    issue_chunk(0);

    #pragma unroll 1
    for (int c = 0; c < PV_NCHUNK; c++) {
        if (c + 1 < PV_NCHUNK) {
            issue_chunk(c + 1);
            cp_wait<1>();
        } else {
            cp_wait<0>();
        }
        __syncthreads();

        const __half* Af = pvsm + (c & 1) * PV_STAGE;
        const __half* Bf = Af + PV_ABUF;
        #pragma unroll
        for (int ks = 0; ks < 4; ks++) {
            wmma::fragment<wmma::matrix_a, 16, 16, 16, __half, wmma::row_major> af[2];
            wmma::fragment<wmma::matrix_b, 16, 16, 16, __half, wmma::row_major> bf[2];
            #pragma unroll
            for (int r2 = 0; r2 < 2; r2++)
                wmma::load_matrix_sync(af[r2], &Af[(wm * 32 + r2 * 16) * PALD + ks * 16], PALD);
            #pragma unroll
            for (int cn = 0; cn < 2; cn++)
                wmma::load_matrix_sync(bf[cn], &Bf[(ks * 16) * PBLD + wn * 32 + cn * 16], PBLD);
            #pragma unroll
            for (int r2 = 0; r2 < 2; r2++)
                #pragma unroll
                for (int cn = 0; cn < 2; cn++)
                    wmma::mma_sync(acc[r2][cn], af[r2], bf[cn], acc[r2][cn]);
        }
        __syncthreads();
    }

    #pragma unroll
    for (int r2 = 0; r2 < 2; r2++)
        #pragma unroll
        for (int cn = 0; cn < 2; cn++)
            wmma::store_matrix_sync(C + (long long)(m0 + wm * 32 + r2 * 16) * CH + n0 + wn * 32 + cn * 16,
                                    acc[r2][cn], CH, wmma::mem_row_major);
}

// ======== scores v3: 64-row tiles + FUSED normalize (beta fp32 + fp16) ===========
// Pass 1: S = g @ f^T streamed raw to gmem, online row max/sumexp per CTA.
// Pass 2 (same CTA): rows are final -> re-read own rows (L2-hot), write
// beta = exp(s-m)/l as fp32 (output) and fp16 (for PV). No normalize kernel.
static constexpr int SLD = 132;
static constexpr int GLD = 72;
static constexpr int SCORES_SMEM = (2 * 64 * GLD + 2 * 128 * GLD) * 2 + 64 * SLD * 4; // 89088 B

__global__ void __launch_bounds__(256, 2)
scores_kernel(const float* __restrict__ g, const float* __restrict__ f,
              float* __restrict__ sraw, __half* __restrict__ betah)
{
    extern __shared__ unsigned char smraw[];
    __nv_bfloat16* Ghi = reinterpret_cast<__nv_bfloat16*>(smraw);
    __nv_bfloat16* Glo = Ghi + 64 * GLD;
    __nv_bfloat16* Fhi = Glo + 64 * GLD;
    __nv_bfloat16* Flo = Fhi + 128 * GLD;
    float*         S   = reinterpret_cast<float*>(Flo + 128 * GLD);

    const int b   = blockIdx.y;
    const int r0  = blockIdx.x * 64;
    const int tid = threadIdx.x;
    const int wid = tid >> 5;
    const int wm  = wid >> 2;
    const int wn  = wid & 3;

    const float* gbase = g + ((long long)b * NTOK + r0) * FGD;
    const float* fbase = f + (long long)b * NTOK * FGD;

    #pragma unroll
    for (int i = 0; i < 4; i++) {
        int idx = tid + i * 256;
        int row = idx >> 4;
        int c4  = (idx & 15) << 2;
        float4 v = *reinterpret_cast<const float4*>(gbase + row * FGD + c4);
        split4(v, &Ghi[row * GLD + c4], &Glo[row * GLD + c4]);
    }

    float m_run = -1e30f, l_run = 0.0f;
    const int srow = tid >> 2;
    const int q    = tid & 3;
    const float4* Sscan4 = reinterpret_cast<const float4*>(&S[srow * SLD + q * 32]);

    for (int ci = 0; ci < 32; ci++) {
        __syncthreads();
        #pragma unroll
        for (int i = 0; i < 8; i++) {
            int idx = tid + i * 256;
            int row = idx >> 4;
            int c4  = (idx & 15) << 2;
            float4 v = *reinterpret_cast<const float4*>(fbase + (long long)(ci * 128 + row) * FGD + c4);
            split4(v, &Fhi[row * GLD + c4], &Flo[row * GLD + c4]);
        }
        __syncthreads();

        wmma::fragment<wmma::accumulator, 16, 16, 16, float> acc[2][2];
        #pragma unroll
        for (int i = 0; i < 2; i++)
            #pragma unroll
            for (int j = 0; j < 2; j++)
                wmma::fill_fragment(acc[i][j], 0.0f);

        #pragma unroll
        for (int ks = 0; ks < 4; ks++) {
            wmma::fragment<wmma::matrix_a, 16, 16, 16, __nv_bfloat16, wmma::row_major> ah[2], al[2];
            wmma::fragment<wmma::matrix_b, 16, 16, 16, __nv_bfloat16, wmma::col_major> bh[2], bl[2];
            #pragma unroll
            for (int r2 = 0; r2 < 2; r2++) {
                wmma::load_matrix_sync(ah[r2], &Ghi[(wm * 32 + r2 * 16) * GLD + ks * 16], GLD);
                wmma::load_matrix_sync(al[r2], &Glo[(wm * 32 + r2 * 16) * GLD + ks * 16], GLD);
            }
            #pragma unroll
            for (int cn = 0; cn < 2; cn++) {
                wmma::load_matrix_sync(bh[cn], &Fhi[(wn * 32 + cn * 16) * GLD + ks * 16], GLD);
                wmma::load_matrix_sync(bl[cn], &Flo[(wn * 32 + cn * 16) * GLD + ks * 16], GLD);
            }
            #pragma unroll
            for (int r2 = 0; r2 < 2; r2++)
                #pragma unroll
                for (int cn = 0; cn < 2; cn++) {
                    wmma::mma_sync(acc[r2][cn], ah[r2], bh[cn], acc[r2][cn]);
                    wmma::mma_sync(acc[r2][cn], ah[r2], bl[cn], acc[r2][cn]);
                    wmma::mma_sync(acc[r2][cn], al[r2], bh[cn], acc[r2][cn]);
                }
        }
        #pragma unroll
        for (int r2 = 0; r2 < 2; r2++)
            #pragma unroll
            for (int cn = 0; cn < 2; cn++)
                wmma::store_matrix_sync(&S[(wm * 32 + r2 * 16) * SLD + wn * 32 + cn * 16],
                                        acc[r2][cn], SLD, wmma::mem_row_major);
        __syncthreads();

        size_t gout = (size_t)(b * NTOK + r0) * NTOK + (size_t)ci * 128;
        #pragma unroll
        for (int i = 0; i < 8; i++) {
            int idx = tid + i * 256;
            int row = idx >> 5;
            int c4  = (idx & 31) << 2;
            float4 v = *reinterpret_cast<const float4*>(&S[row * SLD + c4]);
            *reinterpret_cast<float4*>(sraw + gout + (size_t)row * NTOK + c4) = v;
        }
        float vmax = -1e30f;
        #pragma unroll
        for (int j = 0; j < 8; j++) {
            float4 a = Sscan4[j];
            vmax = fmaxf(vmax, fmaxf(fmaxf(a.x, a.y), fmaxf(a.z, a.w)));
        }
        float mn = fmaxf(m_run, vmax);
        float add = 0.0f;
        #pragma unroll
        for (int j = 0; j < 8; j++) {
            float4 a = Sscan4[j];
            add += __expf(a.x - mn) + __expf(a.y - mn) + __expf(a.z - mn) + __expf(a.w - mn);
        }
        l_run = l_run * __expf(m_run - mn) + add;
        m_run = mn;
    }

    // finalize per-row stats across the 4 lanes of each row
    #pragma unroll
    for (int off = 1; off < 4; off <<= 1) {
        float mo  = __shfl_xor_sync(0xffffffffu, m_run, off);
        float lo2 = __shfl_xor_sync(0xffffffffu, l_run, off);
        float mn  = fmaxf(m_run, mo);
        l_run = l_run * __expf(m_run - mn) + lo2 * __expf(mo - mn);
        m_run = mn;
    }

    // ---- fused normalize pass: this CTA's 64 rows are final ----
    __syncthreads();                       // everyone done reading S for stats
    if (q == 0) {
        S[srow]      = m_run;              // reuse dead S region for per-row m
        S[64 + srow] = 1.0f / l_run;       // and 1/l
    }
    __syncthreads();

    float*  braw = sraw  + ((size_t)(b * NTOK + r0)) * NTOK;   // 64 contiguous rows
    __half* bh16 = betah + ((size_t)(b * NTOK + r0)) * NTOK;
    #pragma unroll 4
    for (int i = 0; i < 256; i++) {        // 64*4096/4 = 65536 float4 / 256 thr
        int idx = tid + i * 256;
        int row = idx >> 10;               // 1024 float4 per row
        float m   = S[row];
        float inv = S[64 + row];
        float4 v = *reinterpret_cast<float4*>(braw + (size_t)idx * 4);
        v.x = __expf(v.x - m) * inv;
        v.y = __expf(v.y - m) * inv;
        v.z = __expf(v.z - m) * inv;
        v.w = __expf(v.w - m) * inv;
        *reinterpret_cast<float4*>(braw + (size_t)idx * 4) = v;
        __half2 h01 = __floats2half2_rn(v.x, v.y);
        __half2 h23 = __floats2half2_rn(v.z, v.w);
        uint2 p;
        p.x = *reinterpret_cast<uint32_t*>(&h01);
        p.y = *reinterpret_cast<uint32_t*>(&h23);
        *reinterpret_cast<uint2*>(bh16 + (size_t)idx * 4) = p;
    }
}

// ================== launch ========================================================
extern "C" void kernel_launch(void* const* d_in, const int* in_sizes, int n_in,
                              void* d_out, int out_size)
{
    (void)in_sizes; (void)n_in;
    const float* l  = (const float*)d_in[0];
    const float* r  = (const float*)d_in[1];
    const float* Wf = (const float*)d_in[2];
    const float* Wg = (const float*)d_in[3];
    const float* Wh = (const float*)d_in[4];
    const float* Wo = (const float*)d_in[5];
    const float* bf = (const float*)d_in[6];
    const float* bg = (const float*)d_in[7];
    const float* bh = (const float*)d_in[8];
    const float* bo = (const float*)d_in[9];
    float* out = (float*)d_out;

    float  *p_f, *p_g, *p_oatt, *p_bscr;
    __half *p_h16, *p_betah;
    cudaGetSymbolAddress((void**)&p_f,     d_f);
    cudaGetSymbolAddress((void**)&p_g,     d_g);
    cudaGetSymbolAddress((void**)&p_h16,   d_h16);
    cudaGetSymbolAddress((void**)&p_betah, d_betah);
    cudaGetSymbolAddress((void**)&p_oatt,  d_oatt);
    cudaGetSymbolAddress((void**)&p_bscr,  d_beta_scratch);

    // output layout: reference returns (o, beta) -> o first, then beta
    float* o_out    = nullptr;
    float* beta_out = nullptr;
    long long osz = (long long)out_size;
    if (osz >= O_ELEMS + B_ELEMS) { o_out = out; beta_out = out + O_ELEMS; }
    else if (osz == B_ELEMS)      { beta_out = out; }
    else                          { o_out = out; beta_out = p_bscr; }

    // one-time setup -- 3 streams (proven zero device-mem delta)
    static cudaStream_t s_main = nullptr, s_side = nullptr, s_aux = nullptr;
    static cudaEvent_t  ev_root = nullptr, ev_side = nullptr, ev_aux = nullptr, ev_main = nullptr;
    if (s_main == nullptr) {
        cudaStreamCreateWithFlags(&s_main, cudaStreamNonBlocking);
        cudaStreamCreateWithFlags(&s_side, cudaStreamNonBlocking);
        cudaStreamCreateWithFlags(&s_aux,  cudaStreamNonBlocking);
        cudaEventCreateWithFlags(&ev_root, cudaEventDisableTiming);
        cudaEventCreateWithFlags(&ev_side, cudaEventDisableTiming);
        cudaEventCreateWithFlags(&ev_aux,  cudaEventDisableTiming);
        cudaEventCreateWithFlags(&ev_main, cudaEventDisableTiming);
        cudaFuncSetAttribute(scores_kernel, cudaFuncAttributeMaxDynamicSharedMemorySize, SCORES_SMEM);
        cudaFuncSetAttribute(pv_f16s_kernel, cudaFuncAttributeMaxDynamicSharedMemorySize, PV_SMEM);
        cudaFuncSetAttribute(gemm_split_kernel, cudaFuncAttributeMaxDynamicSharedMemorySize, GEMM_SMEM);
    }

    // fork from the capture (default) stream
    cudaEventRecord(ev_root, 0);
    cudaStreamWaitEvent(s_main, ev_root, 0);
    cudaStreamWaitEvent(s_side, ev_root, 0);
    cudaStreamWaitEvent(s_aux,  ev_root, 0);

    // side stream: h = relu(l @ Wh + bh) as fp16 (only needed by PV)
    gemm_split_kernel<<<dim3(8, 128, 1), 256, GEMM_SMEM, s_side>>>(l, Wh, bh, nullptr, p_h16, 512, 512, 1);
    cudaEventRecord(ev_side, s_side);

    // aux: f ; main: g  (concurrent, both feed scores)
    gemm_split_kernel<<<dim3(1, 128, 1), 256, GEMM_SMEM, s_aux>>>(l, Wf, bf, p_f, nullptr, 512, 64, 1);
    cudaEventRecord(ev_aux, s_aux);
    gemm_split_kernel<<<dim3(1, 128, 1), 256, GEMM_SMEM, s_main>>>(r, Wg, bg, p_g, nullptr, 512, 64, 1);
    cudaStreamWaitEvent(s_main, ev_aux, 0);

    // main: fused scores+softmax (writes beta fp32 + fp16)
    scores_kernel<<<dim3(64, 4, 1), 256, SCORES_SMEM, s_main>>>(p_g, p_f, beta_out, p_betah);

    // join h before PV
    cudaStreamWaitEvent(s_main, ev_side, 0);
    if (o_out) {
        // o_att = beta @ h  (per batch) -- v4 PV (128x64, KC=64, cp.async)
        pv_f16s_kernel<<<dim3(8, 32, 4), 256, PV_SMEM, s_main>>>(p_betah, p_h16, p_oatt);
        // o = relu(o_att @ Wo + bo)   [16384, 512]
        gemm_split_kernel<<<dim3(8, 128, 1), 256, GEMM_SMEM, s_main>>>(p_oatt, Wo, bo, o_out, nullptr, 512, 512, 1);
    }
    cudaEventRecord(ev_main, s_main);

    // join back to the capture stream
    cudaStreamWaitEvent(0, ev_main, 0);
}

// round 16
// speedup vs baseline: 1.1438x; 1.1329x over previous
#include <cuda_runtime.h>
#include <cuda_bf16.h>
#include <cuda_fp16.h>
#include <mma.h>
#include <cstdint>

using namespace nvcuda;

static constexpr int BATCH = 4;
static constexpr int NTOK  = 4096;   // H*W
static constexpr int CH    = 512;
static constexpr int FGD   = 64;

static constexpr long long O_ELEMS = (long long)BATCH * NTOK * CH;    // 8388608
static constexpr long long B_ELEMS = (long long)BATCH * NTOK * NTOK;  // 67108864
static constexpr long long B_PER_BATCH = (long long)NTOK * NTOK;      // 16777216

// ---------------- scratch (static __device__ -- no allocations allowed) ----------
__device__ float  d_f[(size_t)BATCH * NTOK * FGD];
__device__ float  d_g[(size_t)BATCH * NTOK * FGD];
__device__ __half d_h16[(size_t)BATCH * NTOK * CH];          // h in fp16 (h >= 0)
__device__ __half d_betah[(size_t)BATCH * NTOK * NTOK];      // beta in fp16
__device__ float  d_oatt[(size_t)BATCH * NTOK * CH];
__device__ float  d_rowm[BATCH * NTOK];
__device__ float  d_rowl[BATCH * NTOK];
__device__ float  d_beta_scratch[(size_t)BATCH * NTOK * NTOK]; // only if harness wants o-only

// ---------------- bf16 split helper (x = hi + lo, ~17-bit effective mantissa) ----
__device__ __forceinline__ void split4(const float4 v, __nv_bfloat16* hi, __nv_bfloat16* lo) {
    hi[0] = __float2bfloat16(v.x); lo[0] = __float2bfloat16(v.x - __bfloat162float(hi[0]));
    hi[1] = __float2bfloat16(v.y); lo[1] = __float2bfloat16(v.y - __bfloat162float(hi[1]));
    hi[2] = __float2bfloat16(v.z); lo[2] = __float2bfloat16(v.z - __bfloat162float(hi[2]));
    hi[3] = __float2bfloat16(v.w); lo[3] = __float2bfloat16(v.w - __bfloat162float(hi[3]));
}

// ---------------- fp16 helpers ---------------------------------------------------
__device__ __forceinline__ void split4h(const float4 v, __half* hi, __half* lo) {
    hi[0] = __float2half_rn(v.x); lo[0] = __float2half_rn(v.x - __half2float(hi[0]));
    hi[1] = __float2half_rn(v.y); lo[1] = __float2half_rn(v.y - __half2float(hi[1]));
    hi[2] = __float2half_rn(v.z); lo[2] = __float2half_rn(v.z - __half2float(hi[2]));
    hi[3] = __float2half_rn(v.w); lo[3] = __float2half_rn(v.w - __half2float(hi[3]));
}
__device__ __forceinline__ void cvt4h(const float4 v, __half* o) {
    o[0] = __float2half_rn(v.x); o[1] = __float2half_rn(v.y);
    o[2] = __float2half_rn(v.z); o[3] = __float2half_rn(v.w);
}

// ---------------- cp.async helpers (Ampere path, valid on sm_103) ----------------
__device__ __forceinline__ uint32_t smem_u32(const void* p) {
    uint32_t a;
    asm("{ .reg .u64 t; cvta.to.shared.u64 t, %1; cvt.u32.u64 %0, t; }" : "=r"(a) : "l"(p));
    return a;
}
__device__ __forceinline__ void cp_async16(uint32_t dst, const void* src) {
    asm volatile("cp.async.cg.shared.global [%0], [%1], 16;" :: "r"(dst), "l"(src));
}
__device__ __forceinline__ void cp_commit() {
    asm volatile("cp.async.commit_group;");
}
template <int N>
__device__ __forceinline__ void cp_wait() {
    asm volatile("cp.async.wait_group %0;" :: "n"(N));
}

// ================== generic GEMM v2: C = act(A[M,K] @ B[K,N] + bias) ==============
static constexpr int GBM = 128, GBN = 64, GBK = 32;
static constexpr int ALD = GBK + 8;   // 40
static constexpr int BLD = GBN + 8;   // 72
static constexpr int CLD = GBN + 4;   // 68
static constexpr int G_AHALF = GBM * ALD;              // 5120
static constexpr int G_BHALF = GBK * BLD;              // 2304
static constexpr int G_STAGE = 2 * G_AHALF + 2 * G_BHALF;   // 14848 bf16
static constexpr int GEMM_SMEM = 2 * G_STAGE * 2;      // 59392 B

__global__ void __launch_bounds__(256)
gemm_split_kernel(const float* __restrict__ A, const float* __restrict__ B,
                  const float* __restrict__ bias, float* __restrict__ C,
                  __half* __restrict__ C16,
                  int K, int N, int relu)
{
    extern __shared__ __align__(16) unsigned char gsm[];
    float* Csm = reinterpret_cast<float*>(gsm);

    const int m0  = blockIdx.y * GBM;
    const int n0  = blockIdx.x * GBN;
    const int tid = threadIdx.x;
    const int wid = tid >> 5;
    const int wm  = wid >> 1;
    const int wn  = wid & 1;

    wmma::fragment<wmma::accumulator, 16, 16, 16, float> acc[2][2];
    #pragma unroll
    for (int i = 0; i < 2; i++)
        #pragma unroll
        for (int j = 0; j < 2; j++)
            wmma::fill_fragment(acc[i][j], 0.0f);

    const int NCHUNK = K >> 5;
    float4 ra[4], rb[2];

    #pragma unroll
    for (int i = 0; i < 4; i++) {
        int idx = tid + i * 256;
        int row = idx >> 3;
        int c4  = (idx & 7) << 2;
        ra[i] = *reinterpret_cast<const float4*>(A + (long long)(m0 + row) * K + c4);
    }
    #pragma unroll
    for (int i = 0; i < 2; i++) {
        int idx = tid + i * 256;
        int row = idx >> 4;
        int c4  = (idx & 15) << 2;
        rb[i] = *reinterpret_cast<const float4*>(B + (long long)row * N + n0 + c4);
    }

    #pragma unroll 1
    for (int c = 0; c < NCHUNK; c++) {
        __nv_bfloat16* stage = reinterpret_cast<__nv_bfloat16*>(gsm) + (c & 1) * G_STAGE;
        __nv_bfloat16* Ahi = stage;
        __nv_bfloat16* Alo = Ahi + G_AHALF;
        __nv_bfloat16* Bhi = Alo + G_AHALF;
        __nv_bfloat16* Blo = Bhi + G_BHALF;

        #pragma unroll
        for (int i = 0; i < 4; i++) {
            int idx = tid + i * 256;
            int row = idx >> 3;
            int c4  = (idx & 7) << 2;
            split4(ra[i], &Ahi[row * ALD + c4], &Alo[row * ALD + c4]);
        }
        #pragma unroll
        for (int i = 0; i < 2; i++) {
            int idx = tid + i * 256;
            int row = idx >> 4;
            int c4  = (idx & 15) << 2;
            split4(rb[i], &Bhi[row * BLD + c4], &Blo[row * BLD + c4]);
        }
        __syncthreads();

        if (c + 1 < NCHUNK) {
            const long long k0 = (long long)(c + 1) << 5;
            #pragma unroll
            for (int i = 0; i < 4; i++) {
                int idx = tid + i * 256;
                int row = idx >> 3;
                int c4  = (idx & 7) << 2;
                ra[i] = *reinterpret_cast<const float4*>(A + (long long)(m0 + row) * K + k0 + c4);
            }
            #pragma unroll
            for (int i = 0; i < 2; i++) {
                int idx = tid + i * 256;
                int row = idx >> 4;
                int c4  = (idx & 15) << 2;
                rb[i] = *reinterpret_cast<const float4*>(B + (k0 + row) * N + n0 + c4);
            }
        }

        #pragma unroll
        for (int ks = 0; ks < 2; ks++) {
            wmma::fragment<wmma::matrix_a, 16, 16, 16, __nv_bfloat16, wmma::row_major> ah[2], al[2];
            wmma::fragment<wmma::matrix_b, 16, 16, 16, __nv_bfloat16, wmma::row_major> bh[2], bl[2];
            #pragma unroll
            for (int r2 = 0; r2 < 2; r2++) {
                wmma::load_matrix_sync(ah[r2], &Ahi[(wm * 32 + r2 * 16) * ALD + ks * 16], ALD);
                wmma::load_matrix_sync(al[r2], &Alo[(wm * 32 + r2 * 16) * ALD + ks * 16], ALD);
            }
            #pragma unroll
            for (int cn = 0; cn < 2; cn++) {
                wmma::load_matrix_sync(bh[cn], &Bhi[(ks * 16) * BLD + wn * 32 + cn * 16], BLD);
                wmma::load_matrix_sync(bl[cn], &Blo[(ks * 16) * BLD + wn * 32 + cn * 16], BLD);
            }
            #pragma unroll
            for (int r2 = 0; r2 < 2; r2++)
                #pragma unroll
                for (int cn = 0; cn < 2; cn++) {
                    wmma::mma_sync(acc[r2][cn], ah[r2], bh[cn], acc[r2][cn]);
                    wmma::mma_sync(acc[r2][cn], ah[r2], bl[cn], acc[r2][cn]);
                    wmma::mma_sync(acc[r2][cn], al[r2], bh[cn], acc[r2][cn]);
                }
        }
    }

    __syncthreads();
    #pragma unroll
    for (int r2 = 0; r2 < 2; r2++)
        #pragma unroll
        for (int cn = 0; cn < 2; cn++)
            wmma::store_matrix_sync(&Csm[(wm * 32 + r2 * 16) * CLD + wn * 32 + cn * 16],
                                    acc[r2][cn], CLD, wmma::mem_row_major);
    __syncthreads();

    #pragma unroll
    for (int i = 0; i < 8; i++) {
        int idx = tid + i * 256;
        int row = idx >> 4;
        int c4  = (idx & 15) << 2;
        float4 v = *reinterpret_cast<const float4*>(&Csm[row * CLD + c4]);
        if (bias != nullptr) {
            float4 bv = *reinterpret_cast<const float4*>(bias + n0 + c4);
            v.x += bv.x; v.y += bv.y; v.z += bv.z; v.w += bv.w;
        }
        if (relu) {
            v.x = fmaxf(v.x, 0.f); v.y = fmaxf(v.y, 0.f);
            v.z = fmaxf(v.z, 0.f); v.w = fmaxf(v.w, 0.f);
        }
        if (C16 != nullptr) {
            __half2 h01 = __floats2half2_rn(v.x, v.y);
            __half2 h23 = __floats2half2_rn(v.z, v.w);
            uint2 p;
            p.x = *reinterpret_cast<uint32_t*>(&h01);
            p.y = *reinterpret_cast<uint32_t*>(&h23);
            *reinterpret_cast<uint2*>(C16 + (long long)(m0 + row) * N + n0 + c4) = p;
        } else {
            *reinterpret_cast<float4*>(C + (long long)(m0 + row) * N + n0 + c4) = v;
        }
    }
}

// ============ o-proj GEMM: o = relu(oatt @ Wo + bo), fp16 2-term =================
// A (oatt) fp32 -> fp16 single (convex-combination values, no cancellation in A).
// B (Wo) fp16 hi+lo split (~22-bit). 2 mma per k-step. 128x64 tile, 8 warps.
static constexpr int OALD = 40;    // A smem ld (halves)
static constexpr int OBLD = 72;    // B smem ld (halves)
static constexpr int OPROJ_SMEM_BYTES = 35840;  // Af(10240B) + Bhi/Blo(4608B*2) < Csm(34816B)

__global__ void __launch_bounds__(256)
oproj_f16_kernel(const float* __restrict__ A, const float* __restrict__ B,
                 const float* __restrict__ bias, float* __restrict__ C)
{
    __shared__ __align__(16) unsigned char smbuf[OPROJ_SMEM_BYTES];
    __half* Af  = reinterpret_cast<__half*>(smbuf);
    __half* Bhi = Af + GBM * OALD;
    __half* Blo = Bhi + GBK * OBLD;
    float*  Csm = reinterpret_cast<float*>(smbuf);

    const int m0  = blockIdx.y * GBM;
    const int n0  = blockIdx.x * GBN;
    const int tid = threadIdx.x;
    const int wid = tid >> 5;
    const int wm  = wid >> 1;
    const int wn  = wid & 1;

    wmma::fragment<wmma::accumulator, 16, 16, 16, float> acc[2][2];
    #pragma unroll
    for (int i = 0; i < 2; i++)
        #pragma unroll
        for (int j = 0; j < 2; j++)
            wmma::fill_fragment(acc[i][j], 0.0f);

    for (int kt = 0; kt < CH; kt += GBK) {
        #pragma unroll
        for (int i = 0; i < 4; i++) {
            int idx = tid + i * 256;
            int row = idx >> 3;
            int c4  = (idx & 7) << 2;
            float4 v = *reinterpret_cast<const float4*>(A + (long long)(m0 + row) * CH + kt + c4);
            cvt4h(v, &Af[row * OALD + c4]);
        }
        #pragma unroll
        for (int i = 0; i < 2; i++) {
            int idx = tid + i * 256;
            int row = idx >> 4;
            int c4  = (idx & 15) << 2;
            float4 v = *reinterpret_cast<const float4*>(B + (long long)(kt + row) * CH + n0 + c4);
            split4h(v, &Bhi[row * OBLD + c4], &Blo[row * OBLD + c4]);
        }
        __syncthreads();
        #pragma unroll
        for (int ks = 0; ks < 2; ks++) {
            wmma::fragment<wmma::matrix_a, 16, 16, 16, __half, wmma::row_major> af[2];
            wmma::fragment<wmma::matrix_b, 16, 16, 16, __half, wmma::row_major> bh[2], bl[2];
            #pragma unroll
            for (int r2 = 0; r2 < 2; r2++)
                wmma::load_matrix_sync(af[r2], &Af[(wm * 32 + r2 * 16) * OALD + ks * 16], OALD);
            #pragma unroll
            for (int cn = 0; cn < 2; cn++) {
                wmma::load_matrix_sync(bh[cn], &Bhi[(ks * 16) * OBLD + wn * 32 + cn * 16], OBLD);
                wmma::load_matrix_sync(bl[cn], &Blo[(ks * 16) * OBLD + wn * 32 + cn * 16], OBLD);
            }
            #pragma unroll
            for (int r2 = 0; r2 < 2; r2++)
                #pragma unroll
                for (int cn = 0; cn < 2; cn++) {
                    wmma::mma_sync(acc[r2][cn], af[r2], bh[cn], acc[r2][cn]);
                    wmma::mma_sync(acc[r2][cn], af[r2], bl[cn], acc[r2][cn]);
                }
        }
        __syncthreads();
    }

    #pragma unroll
    for (int r2 = 0; r2 < 2; r2++)
        #pragma unroll
        for (int cn = 0; cn < 2; cn++)
            wmma::store_matrix_sync(&Csm[(wm * 32 + r2 * 16) * CLD + wn * 32 + cn * 16],
                                    acc[r2][cn], CLD, wmma::mem_row_major);
    __syncthreads();

    #pragma unroll
    for (int i = 0; i < 8; i++) {
        int idx = tid + i * 256;
        int row = idx >> 4;
        int c4  = (idx & 15) << 2;
        float4 v = *reinterpret_cast<const float4*>(&Csm[row * CLD + c4]);
        float4 bv = *reinterpret_cast<const float4*>(bias + n0 + c4);
        v.x = fmaxf(v.x + bv.x, 0.f);
        v.y = fmaxf(v.y + bv.y, 0.f);
        v.z = fmaxf(v.z + bv.z, 0.f);
        v.w = fmaxf(v.w + bv.w, 0.f);
        *reinterpret_cast<float4*>(C + (long long)(m0 + row) * CH + n0 + c4) = v;
    }
}

// ================== PV GEMM v4 (proven best): 128x64, KC=64, cp.async ============
static constexpr int PALD = 72;
static constexpr int PBLD = 72;
static constexpr int PV_ABUF = 128 * PALD;
static constexpr int PV_BBUF = 64 * PBLD;
static constexpr int PV_STAGE = PV_ABUF + PV_BBUF;  // 13824 halves
static constexpr int PV_SMEM = 2 * PV_STAGE * 2;    // 55296 B
static constexpr int PV_NCHUNK = NTOK / 64;         // 64

__global__ void __launch_bounds__(256)
pv_f16s_kernel(const __half* __restrict__ betah, const __half* __restrict__ h16,
               float* __restrict__ oatt)
{
    extern __shared__ __align__(16) __half pvsm[];

    const __half* A = betah + (long long)blockIdx.z * NTOK * NTOK;
    const __half* B = h16   + (long long)blockIdx.z * NTOK * CH;
    float*        C = oatt  + (long long)blockIdx.z * NTOK * CH;
    const int m0  = blockIdx.y * 128;
    const int n0  = blockIdx.x * 64;
    const int tid = threadIdx.x;
    const int wid = tid >> 5;
    const int wm  = wid >> 1;
    const int wn  = wid & 1;

    const uint32_t smbase = smem_u32(pvsm);

    auto issue_chunk = [&](int c) {
        const int buf = c & 1;
        uint32_t sa = smbase + (uint32_t)(buf * PV_STAGE) * 2;
        uint32_t sb = sa + (uint32_t)PV_ABUF * 2;
        const long long k0 = (long long)c * 64;
        #pragma unroll
        for (int i = 0; i < 4; i++) {
            int idx = tid + i * 256;
            int row = idx >> 3;
            int c8  = (idx & 7) << 3;
            cp_async16(sa + (uint32_t)(row * PALD + c8) * 2,
                       A + (long long)(m0 + row) * NTOK + k0 + c8);
        }
        #pragma unroll
        for (int i = 0; i < 2; i++) {
            int idx = tid + i * 256;
            int row = idx >> 3;
            int c8  = (idx & 7) << 3;
            cp_async16(sb + (uint32_t)(row * PBLD + c8) * 2,
                       B + (long long)(k0 + row) * CH + n0 + c8);
        }
        cp_commit();
    };

    wmma::fragment<wmma::accumulator, 16, 16, 16, float> acc[2][2];
    #pragma unroll
    for (int i = 0; i < 2; i++)
        #pragma unroll
        for (int j = 0; j < 2; j++)
            wmma::fill_fragment(acc[i][j], 0.0f);

    issue_chunk(0);

    #pragma unroll 1
    for (int c = 0; c < PV_NCHUNK; c++) {
        if (c + 1 < PV_NCHUNK) {
            issue_chunk(c + 1);
            cp_wait<1>();
        } else {
            cp_wait<0>();
        }
        __syncthreads();

        const __half* Af = pvsm + (c & 1) * PV_STAGE;
        const __half* Bf = Af + PV_ABUF;
        #pragma unroll
        for (int ks = 0; ks < 4; ks++) {
            wmma::fragment<wmma::matrix_a, 16, 16, 16, __half, wmma::row_major> af[2];
            wmma::fragment<wmma::matrix_b, 16, 16, 16, __half, wmma::row_major> bf[2];
            #pragma unroll
            for (int r2 = 0; r2 < 2; r2++)
                wmma::load_matrix_sync(af[r2], &Af[(wm * 32 + r2 * 16) * PALD + ks * 16], PALD);
            #pragma unroll
            for (int cn = 0; cn < 2; cn++)
                wmma::load_matrix_sync(bf[cn], &Bf[(ks * 16) * PBLD + wn * 32 + cn * 16], PBLD);
            #pragma unroll
            for (int r2 = 0; r2 < 2; r2++)
                #pragma unroll
                for (int cn = 0; cn < 2; cn++)
                    wmma::mma_sync(acc[r2][cn], af[r2], bf[cn], acc[r2][cn]);
        }
        __syncthreads();
    }

    #pragma unroll
    for (int r2 = 0; r2 < 2; r2++)
        #pragma unroll
        for (int cn = 0; cn < 2; cn++)
            wmma::store_matrix_sync(C + (long long)(m0 + wm * 32 + r2 * 16) * CH + n0 + wn * 32 + cn * 16,
                                    acc[r2][cn], CH, wmma::mem_row_major);
}

// ======== scores v2 (proven): 64-row query tiles, 256 threads ====================
static constexpr int SLD = 132;
static constexpr int GLD = 72;
static constexpr int SCORES_SMEM = (2 * 64 * GLD + 2 * 128 * GLD) * 2 + 64 * SLD * 4; // 89088 B

__global__ void __launch_bounds__(256, 2)
scores_kernel(const float* __restrict__ g, const float* __restrict__ f,
              float* __restrict__ sraw, float* __restrict__ rowm, float* __restrict__ rowl)
{
    extern __shared__ unsigned char smraw[];
    __nv_bfloat16* Ghi = reinterpret_cast<__nv_bfloat16*>(smraw);
    __nv_bfloat16* Glo = Ghi + 64 * GLD;
    __nv_bfloat16* Fhi = Glo + 64 * GLD;
    __nv_bfloat16* Flo = Fhi + 128 * GLD;
    float*         S   = reinterpret_cast<float*>(Flo + 128 * GLD);

    const int b   = blockIdx.y;
    const int r0  = blockIdx.x * 64;
    const int tid = threadIdx.x;
    const int wid = tid >> 5;
    const int wm  = wid >> 2;
    const int wn  = wid & 3;

    const float* gbase = g + ((long long)b * NTOK + r0) * FGD;
    const float* fbase = f + (long long)b * NTOK * FGD;

    #pragma unroll
    for (int i = 0; i < 4; i++) {
        int idx = tid + i * 256;
        int row = idx >> 4;
        int c4  = (idx & 15) << 2;
        float4 v = *reinterpret_cast<const float4*>(gbase + row * FGD + c4);
        split4(v, &Ghi[row * GLD + c4], &Glo[row * GLD + c4]);
    }

    float m_run = -1e30f, l_run = 0.0f;
    const int srow = tid >> 2;
    const int q    = tid & 3;
    const float4* Sscan4 = reinterpret_cast<const float4*>(&S[srow * SLD + q * 32]);

    for (int ci = 0; ci < 32; ci++) {
        __syncthreads();
        #pragma unroll
        for (int i = 0; i < 8; i++) {
            int idx = tid + i * 256;
            int row = idx >> 4;
            int c4  = (idx & 15) << 2;
            float4 v = *reinterpret_cast<const float4*>(fbase + (long long)(ci * 128 + row) * FGD + c4);
            split4(v, &Fhi[row * GLD + c4], &Flo[row * GLD + c4]);
        }
        __syncthreads();

        wmma::fragment<wmma::accumulator, 16, 16, 16, float> acc[2][2];
        #pragma unroll
        for (int i = 0; i < 2; i++)
            #pragma unroll
            for (int j = 0; j < 2; j++)
                wmma::fill_fragment(acc[i][j], 0.0f);

        #pragma unroll
        for (int ks = 0; ks < 4; ks++) {
            wmma::fragment<wmma::matrix_a, 16, 16, 16, __nv_bfloat16, wmma::row_major> ah[2], al[2];
            wmma::fragment<wmma::matrix_b, 16, 16, 16, __nv_bfloat16, wmma::col_major> bh[2], bl[2];
            #pragma unroll
            for (int r2 = 0; r2 < 2; r2++) {
                wmma::load_matrix_sync(ah[r2], &Ghi[(wm * 32 + r2 * 16) * GLD + ks * 16], GLD);
                wmma::load_matrix_sync(al[r2], &Glo[(wm * 32 + r2 * 16) * GLD + ks * 16], GLD);
            }
            #pragma unroll
            for (int cn = 0; cn < 2; cn++) {
                wmma::load_matrix_sync(bh[cn], &Fhi[(wn * 32 + cn * 16) * GLD + ks * 16], GLD);
                wmma::load_matrix_sync(bl[cn], &Flo[(wn * 32 + cn * 16) * GLD + ks * 16], GLD);
            }
            #pragma unroll
            for (int r2 = 0; r2 < 2; r2++)
                #pragma unroll
                for (int cn = 0; cn < 2; cn++) {
                    wmma::mma_sync(acc[r2][cn], ah[r2], bh[cn], acc[r2][cn]);
                    wmma::mma_sync(acc[r2][cn], ah[r2], bl[cn], acc[r2][cn]);
                    wmma::mma_sync(acc[r2][cn], al[r2], bh[cn], acc[r2][cn]);
                }
        }
        #pragma unroll
        for (int r2 = 0; r2 < 2; r2++)
            #pragma unroll
            for (int cn = 0; cn < 2; cn++)
                wmma::store_matrix_sync(&S[(wm * 32 + r2 * 16) * SLD + wn * 32 + cn * 16],
                                        acc[r2][cn], SLD, wmma::mem_row_major);
        __syncthreads();

        size_t gout = (size_t)(b * NTOK + r0) * NTOK + (size_t)ci * 128;
        #pragma unroll
        for (int i = 0; i < 8; i++) {
            int idx = tid + i * 256;
            int row = idx >> 5;
            int c4  = (idx & 31) << 2;
            float4 v = *reinterpret_cast<const float4*>(&S[row * SLD + c4]);
            *reinterpret_cast<float4*>(sraw + gout + (size_t)row * NTOK + c4) = v;
        }
        float vmax = -1e30f;
        #pragma unroll
        for (int j = 0; j < 8; j++) {
            float4 a = Sscan4[j];
            vmax = fmaxf(vmax, fmaxf(fmaxf(a.x, a.y), fmaxf(a.z, a.w)));
        }
        float mn = fmaxf(m_run, vmax);
        float add = 0.0f;
        #pragma unroll
        for (int j = 0; j < 8; j++) {
            float4 a = Sscan4[j];
            add += __expf(a.x - mn) + __expf(a.y - mn) + __expf(a.z - mn) + __expf(a.w - mn);
        }
        l_run = l_run * __expf(m_run - mn) + add;
        m_run = mn;
    }

    #pragma unroll
    for (int off = 1; off < 4; off <<= 1) {
        float mo  = __shfl_xor_sync(0xffffffffu, m_run, off);
        float lo2 = __shfl_xor_sync(0xffffffffu, l_run, off);
        float mn  = fmaxf(m_run, mo);
        l_run = l_run * __expf(m_run - mn) + lo2 * __expf(mo - mn);
        m_run = mn;
    }
    if (q == 0) {
        rowm[b * NTOK + r0 + srow] = m_run;
        rowl[b * NTOK + r0 + srow] = l_run;
    }
}

// ============ normalize: beta = exp(s - m)/l  (fp32 out + fp16 copy) =============
__global__ void __launch_bounds__(256)
normalize_kernel(float* __restrict__ beta, __half* __restrict__ betah,
                 const float* __restrict__ rowm, const float* __restrict__ rowl)
{
    long long idx = (long long)blockIdx.x * 256 + threadIdx.x;
    if (idx >= (B_ELEMS >> 2)) return;
    int rowg = (int)(idx >> 10);
    float m   = __ldg(rowm + rowg);
    float inv = 1.0f / __ldg(rowl + rowg);
    float4 v = *reinterpret_cast<float4*>(beta + idx * 4);
    v.x = __expf(v.x - m) * inv;
    v.y = __expf(v.y - m) * inv;
    v.z = __expf(v.z - m) * inv;
    v.w = __expf(v.w - m) * inv;
    *reinterpret_cast<float4*>(beta + idx * 4) = v;
    __half2 h01 = __floats2half2_rn(v.x, v.y);
    __half2 h23 = __floats2half2_rn(v.z, v.w);
    uint2 p;
    p.x = *reinterpret_cast<uint32_t*>(&h01);
    p.y = *reinterpret_cast<uint32_t*>(&h23);
    *reinterpret_cast<uint2*>(betah + idx * 4) = p;
}

// ================== launch ========================================================
extern "C" void kernel_launch(void* const* d_in, const int* in_sizes, int n_in,
                              void* d_out, int out_size)
{
    (void)in_sizes; (void)n_in;
    const float* l  = (const float*)d_in[0];
    const float* r  = (const float*)d_in[1];
    const float* Wf = (const float*)d_in[2];
    const float* Wg = (const float*)d_in[3];
    const float* Wh = (const float*)d_in[4];
    const float* Wo = (const float*)d_in[5];
    const float* bf = (const float*)d_in[6];
    const float* bg = (const float*)d_in[7];
    const float* bh = (const float*)d_in[8];
    const float* bo = (const float*)d_in[9];
    float* out = (float*)d_out;

    float  *p_f, *p_g, *p_oatt, *p_rowm, *p_rowl, *p_bscr;
    __half *p_h16, *p_betah;
    cudaGetSymbolAddress((void**)&p_f,     d_f);
    cudaGetSymbolAddress((void**)&p_g,     d_g);
    cudaGetSymbolAddress((void**)&p_h16,   d_h16);
    cudaGetSymbolAddress((void**)&p_betah, d_betah);
    cudaGetSymbolAddress((void**)&p_oatt,  d_oatt);
    cudaGetSymbolAddress((void**)&p_rowm,  d_rowm);
    cudaGetSymbolAddress((void**)&p_rowl,  d_rowl);
    cudaGetSymbolAddress((void**)&p_bscr,  d_beta_scratch);

    // output layout: reference returns (o, beta) -> o first, then beta
    float* o_out    = nullptr;
    float* beta_out = nullptr;
    long long osz = (long long)out_size;
    if (osz >= O_ELEMS + B_ELEMS) { o_out = out; beta_out = out + O_ELEMS; }
    else if (osz == B_ELEMS)      { beta_out = out; }
    else                          { o_out = out; beta_out = p_bscr; }

    // one-time setup -- 3 streams (proven zero device-mem delta)
    static cudaStream_t s_main = nullptr, s_side = nullptr, s_aux = nullptr;
    static cudaEvent_t  ev_root = nullptr, ev_side = nullptr, ev_aux = nullptr, ev_main = nullptr;
    if (s_main == nullptr) {
        cudaStreamCreateWithFlags(&s_main, cudaStreamNonBlocking);
        cudaStreamCreateWithFlags(&s_side, cudaStreamNonBlocking);
        cudaStreamCreateWithFlags(&s_aux,  cudaStreamNonBlocking);
        cudaEventCreateWithFlags(&ev_root, cudaEventDisableTiming);
        cudaEventCreateWithFlags(&ev_side, cudaEventDisableTiming);
        cudaEventCreateWithFlags(&ev_aux,  cudaEventDisableTiming);
        cudaEventCreateWithFlags(&ev_main, cudaEventDisableTiming);
        cudaFuncSetAttribute(scores_kernel, cudaFuncAttributeMaxDynamicSharedMemorySize, SCORES_SMEM);
        cudaFuncSetAttribute(pv_f16s_kernel, cudaFuncAttributeMaxDynamicSharedMemorySize, PV_SMEM);
        cudaFuncSetAttribute(gemm_split_kernel, cudaFuncAttributeMaxDynamicSharedMemorySize, GEMM_SMEM);
    }

    // fork from the capture (default) stream
    cudaEventRecord(ev_root, 0);
    cudaStreamWaitEvent(s_main, ev_root, 0);
    cudaStreamWaitEvent(s_side, ev_root, 0);
    cudaStreamWaitEvent(s_aux,  ev_root, 0);

    // side stream: h = relu(l @ Wh + bh) as fp16 (only needed by PV)
    gemm_split_kernel<<<dim3(8, 128, 1), 256, GEMM_SMEM, s_side>>>(l, Wh, bh, nullptr, p_h16, 512, 512, 1);
    cudaEventRecord(ev_side, s_side);

    // aux: f ; main: g  (concurrent, both feed scores)
    gemm_split_kernel<<<dim3(1, 128, 1), 256, GEMM_SMEM, s_aux>>>(l, Wf, bf, p_f, nullptr, 512, 64, 1);
    cudaEventRecord(ev_aux, s_aux);
    gemm_split_kernel<<<dim3(1, 128, 1), 256, GEMM_SMEM, s_main>>>(r, Wg, bg, p_g, nullptr, 512, 64, 1);
    cudaStreamWaitEvent(s_main, ev_aux, 0);

    // main: scores -> normalize
    scores_kernel<<<dim3(64, 4, 1), 256, SCORES_SMEM, s_main>>>(p_g, p_f, beta_out, p_rowm, p_rowl);
    normalize_kernel<<<65536, 256, 0, s_main>>>(beta_out, p_betah, p_rowm, p_rowl);

    // join h before PV
    cudaStreamWaitEvent(s_main, ev_side, 0);
    if (o_out) {
        // o_att = beta @ h  (per batch) -- v4 PV (128x64, KC=64, cp.async)
        pv_f16s_kernel<<<dim3(8, 32, 4), 256, PV_SMEM, s_main>>>(p_betah, p_h16, p_oatt);
        // o = relu(o_att @ Wo + bo)   [16384, 512]  fp16 2-term
        oproj_f16_kernel<<<dim3(8, 128, 1), 256, 0, s_main>>>(p_oatt, Wo, bo, o_out);
    }
    cudaEventRecord(ev_main, s_main);

    // join back to the capture stream
    cudaStreamWaitEvent(0, ev_main, 0);
}